// round 8
// baseline (speedup 1.0000x reference)
#include <cuda_runtime.h>
#include <cuda_bf16.h>

// Problem constants
// B=4, C=512, H=W=64 -> N=4096, CI=256
#define NB   4
#define NC   512
#define NN_  4096
#define NCI  256

typedef unsigned long long u64;

// ---------------------------------------------------------------------------
// Scratch (device globals: allocation inside kernel_launch is forbidden)
// ---------------------------------------------------------------------------
__device__ float g_w  [3 * NCI * NC];            // concat [w_phi; w_theta; w_g]  (768 x 512)
__device__ float g_ptg[NB * 3 * NCI * NN_];      // per batch: rows 0-255 phi, 256-511 theta, 512-767 g
__device__ float g_f  [(long long)NB * NN_ * NN_]; // attention scores / probs (268 MB)
__device__ float g_y  [NB * NCI * NN_];          // y = a @ g^T  (b, ci, N)

// ---------------------------------------------------------------------------
// Packed fp32x2 FMA (Blackwell FFMA2): d = a*b + d elementwise on 2 lanes.
// Only reachable via PTX fma.rn.f32x2 — ptxas never auto-fuses it.
// ---------------------------------------------------------------------------
__device__ __forceinline__ void ffma2(u64& d, u64 a, u64 b) {
    asm("fma.rn.f32x2 %0, %1, %2, %0;" : "+l"(d) : "l"(a), "l"(b));
}
__device__ __forceinline__ u64 dup_f32(float a) {
    u64 r;
    asm("mov.b64 %0, {%1, %1};" : "=l"(r) : "f"(a));
    return r;
}

// ---------------------------------------------------------------------------
// Weight concat: one GEMM for all three projections
// ---------------------------------------------------------------------------
__global__ void concat_w_kernel(const float* __restrict__ a,
                                const float* __restrict__ b,
                                const float* __restrict__ c) {
    int i = blockIdx.x * 256 + threadIdx.x;   // 512 blocks * 256 = 131072 = 256*512
    g_w[i]           = a[i];
    g_w[i + 131072]  = b[i];
    g_w[i + 262144]  = c[i];
}

// ---------------------------------------------------------------------------
// Generic batched SGEMM, 128x128 block tile, BK=8, 8x8 per-thread fragments,
// double-buffered shared memory, FFMA2 (f32x2) inner product.
//   A_KC : A is (M,K) row-major (contraction contiguous). Else A is (K,M) rm.
//   B_NC : B is (K,N) row-major. Else B is (N,K) rm (contraction contiguous).
// All of M, Nn multiples of 128; K multiple of 8.
// ---------------------------------------------------------------------------
template <bool A_KC, bool B_NC>
__global__ void __launch_bounds__(256)
sgemm128(const float* __restrict__ A, const float* __restrict__ B,
         float* __restrict__ C, int M, int Nn, int K,
         int lda, int ldb, int ldc,
         long long sA, long long sB, long long sC)
{
    __shared__ float As[2][8][132];
    __shared__ float Bs[2][8][132];

    const int t  = threadIdx.x;
    const int tx = t & 15;
    const int ty = t >> 4;

    A += (long long)blockIdx.z * sA;
    B += (long long)blockIdx.z * sB;
    C += (long long)blockIdx.z * sC;

    const int m0 = blockIdx.y * 128;
    const int n0 = blockIdx.x * 128;

    // Load-index mapping (each thread moves one float4 per operand per k-tile)
    int a_m, a_k, b_n, b_k;
    if (A_KC) { a_m = t >> 1;  a_k = (t & 1) * 4; }
    else      { a_k = t >> 5;  a_m = (t & 31) * 4; }
    if (B_NC) { b_k = t >> 5;  b_n = (t & 31) * 4; }
    else      { b_n = t >> 1;  b_k = (t & 1) * 4; }

    const float* Ag;
    if (A_KC) Ag = A + (long long)(m0 + a_m) * lda + a_k;
    else      Ag = A + (long long)a_k * lda + m0 + a_m;
    const float* Bg;
    if (B_NC) Bg = B + (long long)b_k * ldb + n0 + b_n;
    else      Bg = B + (long long)(n0 + b_n) * ldb + b_k;

    const long long aStep = A_KC ? 8LL : 8LL * lda;
    const long long bStep = B_NC ? 8LL * ldb : 8LL;

    // Prologue: stage tile 0
    float4 ra = *(const float4*)Ag;
    float4 rb = *(const float4*)Bg;
    if (A_KC) {
        As[0][a_k + 0][a_m] = ra.x; As[0][a_k + 1][a_m] = ra.y;
        As[0][a_k + 2][a_m] = ra.z; As[0][a_k + 3][a_m] = ra.w;
    } else {
        *(float4*)&As[0][a_k][a_m] = ra;
    }
    if (B_NC) {
        *(float4*)&Bs[0][b_k][b_n] = rb;
    } else {
        Bs[0][b_k + 0][b_n] = rb.x; Bs[0][b_k + 1][b_n] = rb.y;
        Bs[0][b_k + 2][b_n] = rb.z; Bs[0][b_k + 3][b_n] = rb.w;
    }
    __syncthreads();

    // acc[i] covers output row i (8 cols) as 4 packed f32x2 pairs.
    // ulonglong2 keeps 16B alignment so the epilogue can reuse float4 stores.
    ulonglong2 acc[8][2];
#pragma unroll
    for (int i = 0; i < 8; i++) {
        acc[i][0] = make_ulonglong2(0ULL, 0ULL);
        acc[i][1] = make_ulonglong2(0ULL, 0ULL);
    }

    const int nT = K >> 3;
    int buf = 0;

    for (int kt = 0; kt < nT; kt++) {
        float4 na, nb;
        const bool has_next = (kt + 1 < nT);
        if (has_next) {
            Ag += aStep; Bg += bStep;
            na = *(const float4*)Ag;
            nb = *(const float4*)Bg;
        }
#pragma unroll
        for (int k = 0; k < 8; k++) {
            float af[8];
            *(float4*)&af[0] = *(const float4*)&As[buf][k][ty * 8];
            *(float4*)&af[4] = *(const float4*)&As[buf][k][ty * 8 + 4];
            // B pairs: adjacent columns are naturally adjacent in shared
            ulonglong2 b01 = *(const ulonglong2*)&Bs[buf][k][tx * 8];
            ulonglong2 b23 = *(const ulonglong2*)&Bs[buf][k][tx * 8 + 4];
#pragma unroll
            for (int i = 0; i < 8; i++) {
                u64 ad = dup_f32(af[i]);            // (a,a) — ALU pipe, overlaps fma pipe
                ffma2(acc[i][0].x, ad, b01.x);
                ffma2(acc[i][0].y, ad, b01.y);
                ffma2(acc[i][1].x, ad, b23.x);
                ffma2(acc[i][1].y, ad, b23.y);
            }
        }
        if (has_next) {
            const int nbuf = buf ^ 1;
            if (A_KC) {
                As[nbuf][a_k + 0][a_m] = na.x; As[nbuf][a_k + 1][a_m] = na.y;
                As[nbuf][a_k + 2][a_m] = na.z; As[nbuf][a_k + 3][a_m] = na.w;
            } else {
                *(float4*)&As[nbuf][a_k][a_m] = na;
            }
            if (B_NC) {
                *(float4*)&Bs[nbuf][b_k][b_n] = nb;
            } else {
                Bs[nbuf][b_k + 0][b_n] = nb.x; Bs[nbuf][b_k + 1][b_n] = nb.y;
                Bs[nbuf][b_k + 2][b_n] = nb.z; Bs[nbuf][b_k + 3][b_n] = nb.w;
            }
            __syncthreads();
            buf = nbuf;
        }
    }

    // Epilogue: packed pairs are already (col j, col j+1) -> direct float4 stores
#pragma unroll
    for (int i = 0; i < 8; i++) {
        long long row = (long long)(m0 + ty * 8 + i) * ldc + n0 + tx * 8;
        *(float4*)&C[row]     = *(const float4*)&acc[i][0];
        *(float4*)&C[row + 4] = *(const float4*)&acc[i][1];
    }
}

// ---------------------------------------------------------------------------
// Softmax over rows of 4096. Polynomial exp (7 FMA) instead of MUFU.EX2:
// EX2 is rt=8/SMSP on sm_103a -> only ~140G exp/s chip-wide; FMA path is ~25x.
// Already 78.9% of HBM — leave as is.
// ---------------------------------------------------------------------------
__device__ __forceinline__ float fast_exp(float x) {
    float t = x * 1.4426950408889634f;       // x * log2(e), t <= 0 here
    t = fmaxf(t, -126.0f);
    float fi = floorf(t);
    float fr = (t - fi) * 0.6931471805599453f;   // fr in [0, ln2)
    float p = 1.0f / 720.0f;
    p = fmaf(p, fr, 1.0f / 120.0f);
    p = fmaf(p, fr, 1.0f / 24.0f);
    p = fmaf(p, fr, 1.0f / 6.0f);
    p = fmaf(p, fr, 0.5f);
    p = fmaf(p, fr, 1.0f);
    p = fmaf(p, fr, 1.0f);
    int n = (int)fi;
    return p * __int_as_float((n + 127) << 23);
}

__global__ void __launch_bounds__(256) softmax_kernel(float* __restrict__ f) {
    float* p = f + (long long)blockIdx.x * NN_;
    const int t = threadIdx.x;
    float v[16];
    float mx = -3.4e38f;
#pragma unroll
    for (int i = 0; i < 16; i++) {
        v[i] = p[i * 256 + t];               // coalesced: stride-256 per-thread subset
        mx = fmaxf(mx, v[i]);
    }
#pragma unroll
    for (int o = 16; o > 0; o >>= 1)
        mx = fmaxf(mx, __shfl_xor_sync(0xffffffffu, mx, o));
    __shared__ float sred[8];
    if ((t & 31) == 0) sred[t >> 5] = mx;
    __syncthreads();
#pragma unroll
    for (int i = 0; i < 8; i++) mx = fmaxf(mx, sred[i]);
    __syncthreads();                          // protect sred before reuse

    float s = 0.0f;
#pragma unroll
    for (int i = 0; i < 16; i++) { v[i] = fast_exp(v[i] - mx); s += v[i]; }
#pragma unroll
    for (int o = 16; o > 0; o >>= 1)
        s += __shfl_xor_sync(0xffffffffu, s, o);
    if ((t & 31) == 0) sred[t >> 5] = s;
    __syncthreads();
    s = 0.0f;
#pragma unroll
    for (int i = 0; i < 8; i++) s += sred[i];

    const float inv = 1.0f / s;
#pragma unroll
    for (int i = 0; i < 16; i++) p[i * 256 + t] = v[i] * inv;
}

// ---------------------------------------------------------------------------
// kernel_launch: graph-capturable (kernel launches only; no sync, no alloc)
// ---------------------------------------------------------------------------
extern "C" void kernel_launch(void* const* d_in, const int* in_sizes, int n_in,
                              void* d_out, int out_size) {
    (void)in_sizes; (void)n_in; (void)out_size;
    const float* x       = (const float*)d_in[0];
    const float* w_phi   = (const float*)d_in[1];
    const float* w_theta = (const float*)d_in[2];
    const float* w_g     = (const float*)d_in[3];
    const float* w_mask  = (const float*)d_in[4];
    float* out = (float*)d_out;

    float *wcat, *ptg, *f, *y;
    cudaGetSymbolAddress((void**)&wcat, g_w);
    cudaGetSymbolAddress((void**)&ptg,  g_ptg);
    cudaGetSymbolAddress((void**)&f,    g_f);
    cudaGetSymbolAddress((void**)&y,    g_y);

    // 1) concat projection weights -> one fused projection GEMM
    concat_w_kernel<<<512, 256>>>(w_phi, w_theta, w_g);

    // 2) [phi;theta;g] = Wcat(768x512) @ x[b](512x4096)   -> g_ptg (b,768,4096)
    sgemm128<true, true><<<dim3(32, 6, NB), 256>>>(
        wcat, x, ptg, 768, NN_, NC,
        NC, NN_, NN_, 0LL, (long long)NC * NN_, 768LL * NN_);

    // 3) f[n,m] = sum_c theta[c,n] * phi[c,m]   (TN: A is K-major)
    sgemm128<false, true><<<dim3(32, 32, NB), 256>>>(
        ptg + NCI * NN_, ptg, f, NN_, NN_, NCI,
        NN_, NN_, NN_, 768LL * NN_, 768LL * NN_, (long long)NN_ * NN_);

    // 4) softmax over last axis, in place
    softmax_kernel<<<NB * NN_, 256>>>(f);

    // 5) y[c,n] = sum_m g[c,m] * a[n,m]   (NT: B contraction-contiguous)
    sgemm128<true, false><<<dim3(32, 2, NB), 256>>>(
        ptg + 2 * NCI * NN_, f, y, NCI, NN_, NN_,
        NN_, NN_, NN_, 768LL * NN_, (long long)NN_ * NN_, (long long)NCI * NN_);

    // 6) out[o,n] = sum_c w_mask[o,c] * y[c,n]
    sgemm128<true, true><<<dim3(32, 4, NB), 256>>>(
        w_mask, y, out, NC, NN_, NCI,
        NCI, NN_, NN_, 0LL, (long long)NCI * NN_, (long long)NC * NN_);
}

// round 9
// speedup vs baseline: 2.9670x; 2.9670x over previous
#include <cuda_runtime.h>
#include <cuda_bf16.h>
#include <cstdint>

// Problem constants
// B=4, C=512, H=W=64 -> N=4096, CI=256
#define NB   4
#define NC   512
#define NN_  4096
#define NCI  256

// ---------------------------------------------------------------------------
// Scratch (device globals: allocation inside kernel_launch is forbidden)
// ---------------------------------------------------------------------------
__device__ float g_w  [3 * NCI * NC];              // concat [w_phi; w_theta; w_g]  (768 x 512)
__device__ float g_ptg[NB * 3 * NCI * NN_];        // per batch: rows 0-255 phi, 256-511 theta, 512-767 g
__device__ float g_f  [(long long)NB * NN_ * NN_]; // attention scores / probs (268 MB)
__device__ float g_y  [NB * NCI * NN_];            // y = a @ g^T  (b, ci, N)

// ---------------------------------------------------------------------------
// Weight concat: one GEMM for all three projections
// ---------------------------------------------------------------------------
__global__ void concat_w_kernel(const float* __restrict__ a,
                                const float* __restrict__ b,
                                const float* __restrict__ c) {
    int i = blockIdx.x * 256 + threadIdx.x;
    g_w[i]           = a[i];
    g_w[i + 131072]  = b[i];
    g_w[i + 262144]  = c[i];
}

// ---------------------------------------------------------------------------
// TF32 helpers
// ---------------------------------------------------------------------------
__device__ __forceinline__ uint32_t f2tf32(float f) {
    uint32_t r;
    asm("cvt.rna.tf32.f32 %0, %1;" : "=r"(r) : "f"(f));
    return r;
}

__device__ __forceinline__ void mma8(float* d, const uint32_t* a, const uint32_t* b) {
    asm volatile(
        "mma.sync.aligned.m16n8k8.row.col.f32.tf32.tf32.f32 "
        "{%0,%1,%2,%3}, {%4,%5,%6,%7}, {%8,%9}, {%0,%1,%2,%3};"
        : "+f"(d[0]), "+f"(d[1]), "+f"(d[2]), "+f"(d[3])
        : "r"(a[0]), "r"(a[1]), "r"(a[2]), "r"(a[3]), "r"(b[0]), "r"(b[1]));
}

// ---------------------------------------------------------------------------
// TF32 tensor-core GEMM. Block tile 128x128, BK=16, 8 warps (2m x 4n),
// warp tile 64x32 via m16n8k8. Double-buffered SMEM, tf32 conversion at the
// SMEM-store stage. Pitch 136 words -> frag LDS bank = 8*tg + g: conflict-free.
//   A_KC : A is (M,K) row-major (contraction contiguous). Else A is (K,M) rm.
//   B_NC : B is (K,N) row-major. Else B is (N,K) rm (contraction contiguous).
// M, Nn multiples of 128; K multiple of 16.
// ---------------------------------------------------------------------------
template <bool A_KC, bool B_NC>
__global__ void __launch_bounds__(256, 2)
tc_gemm(const float* __restrict__ A, const float* __restrict__ B,
        float* __restrict__ C, int M, int Nn, int K,
        int lda, int ldb, int ldc,
        long long sA, long long sB, long long sC)
{
    __shared__ uint32_t As[2][16][136];
    __shared__ uint32_t Bs[2][16][136];

    const int t    = threadIdx.x;
    const int lane = t & 31;
    const int wid  = t >> 5;
    const int wm   = wid >> 2;       // 0..1  -> 64-row slab
    const int wn   = wid & 3;        // 0..3  -> 32-col slab
    const int g    = lane >> 2;      // 0..7
    const int tg   = lane & 3;       // 0..3

    A += (long long)blockIdx.z * sA;
    B += (long long)blockIdx.z * sB;
    C += (long long)blockIdx.z * sC;

    const int m0 = blockIdx.y * 128;
    const int n0 = blockIdx.x * 128;

    // ---- global->smem staging indices (2 float4 per thread per operand) ----
    long long aoff0, aoff1, boff0, boff1, aStep, bStep;
    if (A_KC) {                       // A[m][k], k contiguous
        int m_ = t >> 2, k4 = (t & 3) * 4;
        aoff0 = (long long)(m0 + m_) * lda + k4;
        aoff1 = (long long)(m0 + m_ + 64) * lda + k4;
        aStep = 16;
    } else {                          // A[k][m], m contiguous
        int kr = t >> 5, m4 = (t & 31) * 4;
        aoff0 = (long long)kr * lda + m0 + m4;
        aoff1 = (long long)(kr + 8) * lda + m0 + m4;
        aStep = 16LL * lda;
    }
    if (B_NC) {                       // B[k][n], n contiguous
        int kr = t >> 5, n4 = (t & 31) * 4;
        boff0 = (long long)kr * ldb + n0 + n4;
        boff1 = (long long)(kr + 8) * ldb + n0 + n4;
        bStep = 16LL * ldb;
    } else {                          // B[n][k], k contiguous
        int n_ = t >> 2, k4 = (t & 3) * 4;
        boff0 = (long long)(n0 + n_) * ldb + k4;
        boff1 = (long long)(n0 + n_ + 64) * ldb + k4;
        bStep = 16;
    }

    auto storeA = [&](int buf, float4 v0, float4 v1) {
        if constexpr (A_KC) {
            int m_ = t >> 2, k4 = (t & 3) * 4;
            As[buf][k4 + 0][m_] = f2tf32(v0.x);
            As[buf][k4 + 1][m_] = f2tf32(v0.y);
            As[buf][k4 + 2][m_] = f2tf32(v0.z);
            As[buf][k4 + 3][m_] = f2tf32(v0.w);
            As[buf][k4 + 0][m_ + 64] = f2tf32(v1.x);
            As[buf][k4 + 1][m_ + 64] = f2tf32(v1.y);
            As[buf][k4 + 2][m_ + 64] = f2tf32(v1.z);
            As[buf][k4 + 3][m_ + 64] = f2tf32(v1.w);
        } else {
            int kr = t >> 5, m4 = (t & 31) * 4;
            uint4 u0 = make_uint4(f2tf32(v0.x), f2tf32(v0.y), f2tf32(v0.z), f2tf32(v0.w));
            uint4 u1 = make_uint4(f2tf32(v1.x), f2tf32(v1.y), f2tf32(v1.z), f2tf32(v1.w));
            *(uint4*)&As[buf][kr][m4]     = u0;
            *(uint4*)&As[buf][kr + 8][m4] = u1;
        }
    };
    auto storeB = [&](int buf, float4 v0, float4 v1) {
        if constexpr (B_NC) {
            int kr = t >> 5, n4 = (t & 31) * 4;
            uint4 u0 = make_uint4(f2tf32(v0.x), f2tf32(v0.y), f2tf32(v0.z), f2tf32(v0.w));
            uint4 u1 = make_uint4(f2tf32(v1.x), f2tf32(v1.y), f2tf32(v1.z), f2tf32(v1.w));
            *(uint4*)&Bs[buf][kr][n4]     = u0;
            *(uint4*)&Bs[buf][kr + 8][n4] = u1;
        } else {
            int n_ = t >> 2, k4 = (t & 3) * 4;
            Bs[buf][k4 + 0][n_] = f2tf32(v0.x);
            Bs[buf][k4 + 1][n_] = f2tf32(v0.y);
            Bs[buf][k4 + 2][n_] = f2tf32(v0.z);
            Bs[buf][k4 + 3][n_] = f2tf32(v0.w);
            Bs[buf][k4 + 0][n_ + 64] = f2tf32(v1.x);
            Bs[buf][k4 + 1][n_ + 64] = f2tf32(v1.y);
            Bs[buf][k4 + 2][n_ + 64] = f2tf32(v1.z);
            Bs[buf][k4 + 3][n_ + 64] = f2tf32(v1.w);
        }
    };

    // ---- prologue: stage 0 ----
    {
        float4 a0 = *(const float4*)(A + aoff0);
        float4 a1 = *(const float4*)(A + aoff1);
        float4 b0 = *(const float4*)(B + boff0);
        float4 b1 = *(const float4*)(B + boff1);
        storeA(0, a0, a1);
        storeB(0, b0, b1);
    }
    __syncthreads();

    float acc[4][4][4];
#pragma unroll
    for (int mi = 0; mi < 4; mi++)
#pragma unroll
        for (int ni = 0; ni < 4; ni++)
#pragma unroll
            for (int r = 0; r < 4; r++) acc[mi][ni][r] = 0.0f;

    const int nT = K >> 4;
    int buf = 0;

    for (int kt = 0; kt < nT; kt++) {
        const bool nxt = (kt + 1 < nT);
        float4 na0, na1, nb0, nb1;
        if (nxt) {
            aoff0 += aStep; aoff1 += aStep;
            boff0 += bStep; boff1 += bStep;
            na0 = *(const float4*)(A + aoff0);
            na1 = *(const float4*)(A + aoff1);
            nb0 = *(const float4*)(B + boff0);
            nb1 = *(const float4*)(B + boff1);
        }

#pragma unroll
        for (int kk = 0; kk < 16; kk += 8) {
            uint32_t afr[4][4], bfr[4][2];
#pragma unroll
            for (int mi = 0; mi < 4; mi++) {
                int mc = wm * 64 + mi * 16 + g;
                afr[mi][0] = As[buf][kk + tg][mc];
                afr[mi][1] = As[buf][kk + tg][mc + 8];
                afr[mi][2] = As[buf][kk + tg + 4][mc];
                afr[mi][3] = As[buf][kk + tg + 4][mc + 8];
            }
#pragma unroll
            for (int ni = 0; ni < 4; ni++) {
                int nc = wn * 32 + ni * 8 + g;
                bfr[ni][0] = Bs[buf][kk + tg][nc];
                bfr[ni][1] = Bs[buf][kk + tg + 4][nc];
            }
#pragma unroll
            for (int mi = 0; mi < 4; mi++)
#pragma unroll
                for (int ni = 0; ni < 4; ni++)
                    mma8(acc[mi][ni], afr[mi], bfr[ni]);
        }

        if (nxt) {
            storeA(buf ^ 1, na0, na1);
            storeB(buf ^ 1, nb0, nb1);
            __syncthreads();
            buf ^= 1;
        }
    }

    // ---- epilogue ----
#pragma unroll
    for (int mi = 0; mi < 4; mi++) {
#pragma unroll
        for (int ni = 0; ni < 4; ni++) {
            int row = m0 + wm * 64 + mi * 16 + g;
            int col = n0 + wn * 32 + ni * 8 + 2 * tg;
            float2 lo = make_float2(acc[mi][ni][0], acc[mi][ni][1]);
            float2 hi = make_float2(acc[mi][ni][2], acc[mi][ni][3]);
            *(float2*)&C[(long long)row * ldc + col]       = lo;
            *(float2*)&C[(long long)(row + 8) * ldc + col] = hi;
        }
    }
}

// ---------------------------------------------------------------------------
// Scalar fp32 SGEMM (R6 version, reverted from FFMA2): used for the
// projection and mask GEMMs to keep input/output quantization out of the
// error budget. 128x128 tile, BK=8, 8x8 frags, double-buffered.
// ---------------------------------------------------------------------------
template <bool A_KC, bool B_NC>
__global__ void __launch_bounds__(256)
sgemm128(const float* __restrict__ A, const float* __restrict__ B,
         float* __restrict__ C, int M, int Nn, int K,
         int lda, int ldb, int ldc,
         long long sA, long long sB, long long sC)
{
    __shared__ float As[2][8][132];
    __shared__ float Bs[2][8][132];

    const int t  = threadIdx.x;
    const int tx = t & 15;
    const int ty = t >> 4;

    A += (long long)blockIdx.z * sA;
    B += (long long)blockIdx.z * sB;
    C += (long long)blockIdx.z * sC;

    const int m0 = blockIdx.y * 128;
    const int n0 = blockIdx.x * 128;

    int a_m, a_k, b_n, b_k;
    if (A_KC) { a_m = t >> 1;  a_k = (t & 1) * 4; }
    else      { a_k = t >> 5;  a_m = (t & 31) * 4; }
    if (B_NC) { b_k = t >> 5;  b_n = (t & 31) * 4; }
    else      { b_n = t >> 1;  b_k = (t & 1) * 4; }

    const float* Ag;
    if (A_KC) Ag = A + (long long)(m0 + a_m) * lda + a_k;
    else      Ag = A + (long long)a_k * lda + m0 + a_m;
    const float* Bg;
    if (B_NC) Bg = B + (long long)b_k * ldb + n0 + b_n;
    else      Bg = B + (long long)(n0 + b_n) * ldb + b_k;

    const long long aStep = A_KC ? 8LL : 8LL * lda;
    const long long bStep = B_NC ? 8LL * ldb : 8LL;

    float4 ra = *(const float4*)Ag;
    float4 rb = *(const float4*)Bg;
    if (A_KC) {
        As[0][a_k + 0][a_m] = ra.x; As[0][a_k + 1][a_m] = ra.y;
        As[0][a_k + 2][a_m] = ra.z; As[0][a_k + 3][a_m] = ra.w;
    } else {
        *(float4*)&As[0][a_k][a_m] = ra;
    }
    if (B_NC) {
        *(float4*)&Bs[0][b_k][b_n] = rb;
    } else {
        Bs[0][b_k + 0][b_n] = rb.x; Bs[0][b_k + 1][b_n] = rb.y;
        Bs[0][b_k + 2][b_n] = rb.z; Bs[0][b_k + 3][b_n] = rb.w;
    }
    __syncthreads();

    float acc[8][8];
#pragma unroll
    for (int i = 0; i < 8; i++)
#pragma unroll
        for (int j = 0; j < 8; j++) acc[i][j] = 0.0f;

    const int nT = K >> 3;
    int buf = 0;

    for (int kt = 0; kt < nT; kt++) {
        float4 na, nb;
        const bool has_next = (kt + 1 < nT);
        if (has_next) {
            Ag += aStep; Bg += bStep;
            na = *(const float4*)Ag;
            nb = *(const float4*)Bg;
        }
#pragma unroll
        for (int k = 0; k < 8; k++) {
            float af[8], bf[8];
            *(float4*)&af[0] = *(const float4*)&As[buf][k][ty * 8];
            *(float4*)&af[4] = *(const float4*)&As[buf][k][ty * 8 + 4];
            *(float4*)&bf[0] = *(const float4*)&Bs[buf][k][tx * 8];
            *(float4*)&bf[4] = *(const float4*)&Bs[buf][k][tx * 8 + 4];
#pragma unroll
            for (int i = 0; i < 8; i++)
#pragma unroll
                for (int j = 0; j < 8; j++)
                    acc[i][j] = fmaf(af[i], bf[j], acc[i][j]);
        }
        if (has_next) {
            const int nbuf = buf ^ 1;
            if (A_KC) {
                As[nbuf][a_k + 0][a_m] = na.x; As[nbuf][a_k + 1][a_m] = na.y;
                As[nbuf][a_k + 2][a_m] = na.z; As[nbuf][a_k + 3][a_m] = na.w;
            } else {
                *(float4*)&As[nbuf][a_k][a_m] = na;
            }
            if (B_NC) {
                *(float4*)&Bs[nbuf][b_k][b_n] = nb;
            } else {
                Bs[nbuf][b_k + 0][b_n] = nb.x; Bs[nbuf][b_k + 1][b_n] = nb.y;
                Bs[nbuf][b_k + 2][b_n] = nb.z; Bs[nbuf][b_k + 3][b_n] = nb.w;
            }
            __syncthreads();
            buf = nbuf;
        }
    }

#pragma unroll
    for (int i = 0; i < 8; i++) {
        long long row = (long long)(m0 + ty * 8 + i) * ldc + n0 + tx * 8;
        float4 c0 = make_float4(acc[i][0], acc[i][1], acc[i][2], acc[i][3]);
        float4 c1 = make_float4(acc[i][4], acc[i][5], acc[i][6], acc[i][7]);
        *(float4*)&C[row]     = c0;
        *(float4*)&C[row + 4] = c1;
    }
}

// ---------------------------------------------------------------------------
// Softmax over rows of 4096 (HBM-bound at 78.9% already — unchanged).
// Polynomial exp instead of MUFU.EX2 (EX2 rt=8/SMSP on sm_103a).
// ---------------------------------------------------------------------------
__device__ __forceinline__ float fast_exp(float x) {
    float t = x * 1.4426950408889634f;
    t = fmaxf(t, -126.0f);
    float fi = floorf(t);
    float fr = (t - fi) * 0.6931471805599453f;
    float p = 1.0f / 720.0f;
    p = fmaf(p, fr, 1.0f / 120.0f);
    p = fmaf(p, fr, 1.0f / 24.0f);
    p = fmaf(p, fr, 1.0f / 6.0f);
    p = fmaf(p, fr, 0.5f);
    p = fmaf(p, fr, 1.0f);
    p = fmaf(p, fr, 1.0f);
    int n = (int)fi;
    return p * __int_as_float((n + 127) << 23);
}

__global__ void __launch_bounds__(256) softmax_kernel(float* __restrict__ f) {
    float* p = f + (long long)blockIdx.x * NN_;
    const int t = threadIdx.x;
    float v[16];
    float mx = -3.4e38f;
#pragma unroll
    for (int i = 0; i < 16; i++) {
        v[i] = p[i * 256 + t];
        mx = fmaxf(mx, v[i]);
    }
#pragma unroll
    for (int o = 16; o > 0; o >>= 1)
        mx = fmaxf(mx, __shfl_xor_sync(0xffffffffu, mx, o));
    __shared__ float sred[8];
    if ((t & 31) == 0) sred[t >> 5] = mx;
    __syncthreads();
#pragma unroll
    for (int i = 0; i < 8; i++) mx = fmaxf(mx, sred[i]);
    __syncthreads();

    float s = 0.0f;
#pragma unroll
    for (int i = 0; i < 16; i++) { v[i] = fast_exp(v[i] - mx); s += v[i]; }
#pragma unroll
    for (int o = 16; o > 0; o >>= 1)
        s += __shfl_xor_sync(0xffffffffu, s, o);
    if ((t & 31) == 0) sred[t >> 5] = s;
    __syncthreads();
    s = 0.0f;
#pragma unroll
    for (int i = 0; i < 8; i++) s += sred[i];

    const float inv = 1.0f / s;
#pragma unroll
    for (int i = 0; i < 16; i++) p[i * 256 + t] = v[i] * inv;
}

// ---------------------------------------------------------------------------
// kernel_launch: graph-capturable (kernel launches only; no sync, no alloc)
// ---------------------------------------------------------------------------
extern "C" void kernel_launch(void* const* d_in, const int* in_sizes, int n_in,
                              void* d_out, int out_size) {
    (void)in_sizes; (void)n_in; (void)out_size;
    const float* x       = (const float*)d_in[0];
    const float* w_phi   = (const float*)d_in[1];
    const float* w_theta = (const float*)d_in[2];
    const float* w_g     = (const float*)d_in[3];
    const float* w_mask  = (const float*)d_in[4];
    float* out = (float*)d_out;

    float *wcat, *ptg, *f, *y;
    cudaGetSymbolAddress((void**)&wcat, g_w);
    cudaGetSymbolAddress((void**)&ptg,  g_ptg);
    cudaGetSymbolAddress((void**)&f,    g_f);
    cudaGetSymbolAddress((void**)&y,    g_y);

    // 1) concat projection weights -> one fused projection GEMM
    concat_w_kernel<<<512, 256>>>(w_phi, w_theta, w_g);

    // 2) [phi;theta;g] = Wcat(768x512) @ x[b](512x4096)  (fp32 scalar)
    sgemm128<true, true><<<dim3(32, 6, NB), 256>>>(
        wcat, x, ptg, 768, NN_, NC,
        NC, NN_, NN_, 0LL, (long long)NC * NN_, 768LL * NN_);

    // 3) f[n,m] = sum_c theta[c,n] * phi[c,m]   (TF32 tensor cores)
    tc_gemm<false, true><<<dim3(32, 32, NB), 256>>>(
        ptg + NCI * NN_, ptg, f, NN_, NN_, NCI,
        NN_, NN_, NN_, 768LL * NN_, 768LL * NN_, (long long)NN_ * NN_);

    // 4) softmax over last axis, in place
    softmax_kernel<<<NB * NN_, 256>>>(f);

    // 5) y[c,n] = sum_m g[c,m] * a[n,m]   (TF32 tensor cores)
    tc_gemm<true, false><<<dim3(32, 2, NB), 256>>>(
        ptg + 2 * NCI * NN_, f, y, NCI, NN_, NN_,
        NN_, NN_, NN_, 768LL * NN_, (long long)NN_ * NN_, (long long)NCI * NN_);

    // 6) out[o,n] = sum_c w_mask[o,c] * y[c,n]  (fp32 scalar)
    sgemm128<true, true><<<dim3(32, 4, NB), 256>>>(
        w_mask, y, out, NC, NN_, NCI,
        NCI, NN_, NN_, 0LL, (long long)NCI * NN_, (long long)NC * NN_);
}

// round 10
// speedup vs baseline: 2.9740x; 1.0024x over previous
#include <cuda_runtime.h>
#include <cuda_bf16.h>
#include <cstdint>

// Problem constants
// B=4, C=512, H=W=64 -> N=4096, CI=256
#define NB   4
#define NC   512
#define NN_  4096
#define NCI  256

// ---------------------------------------------------------------------------
// Scratch (device globals: allocation inside kernel_launch is forbidden)
// ---------------------------------------------------------------------------
__device__ float g_w  [3 * NCI * NC];              // concat [w_phi; w_theta; w_g]  (768 x 512)
__device__ float g_ptg[NB * 3 * NCI * NN_];        // per batch: rows 0-255 phi, 256-511 theta, 512-767 g
__device__ float g_f  [(long long)NB * NN_ * NN_]; // attention scores / probs (268 MB)
__device__ float g_y  [NB * NCI * NN_];            // y = a @ g^T  (b, ci, N)

// ---------------------------------------------------------------------------
// Weight concat: one GEMM for all three projections
// ---------------------------------------------------------------------------
__global__ void concat_w_kernel(const float* __restrict__ a,
                                const float* __restrict__ b,
                                const float* __restrict__ c) {
    int i = blockIdx.x * 256 + threadIdx.x;
    g_w[i]           = a[i];
    g_w[i + 131072]  = b[i];
    g_w[i + 262144]  = c[i];
}

// ---------------------------------------------------------------------------
// TF32 helpers
// ---------------------------------------------------------------------------
__device__ __forceinline__ uint32_t f2tf32(float f) {
    uint32_t r;
    asm("cvt.rna.tf32.f32 %0, %1;" : "=r"(r) : "f"(f));
    return r;
}

__device__ __forceinline__ void mma8(float* d, const uint32_t* a, const uint32_t* b) {
    asm volatile(
        "mma.sync.aligned.m16n8k8.row.col.f32.tf32.tf32.f32 "
        "{%0,%1,%2,%3}, {%4,%5,%6,%7}, {%8,%9}, {%0,%1,%2,%3};"
        : "+f"(d[0]), "+f"(d[1]), "+f"(d[2]), "+f"(d[3])
        : "r"(a[0]), "r"(a[1]), "r"(a[2]), "r"(a[3]), "r"(b[0]), "r"(b[1]));
}

// ---------------------------------------------------------------------------
// TF32 tensor-core GEMM. Block tile 128x128, BK=16, 8 warps (2m x 4n),
// warp tile 64x32 via m16n8k8. Double-buffered SMEM, tf32 conversion at the
// SMEM-store stage. Pitch 136 words -> frag LDS bank = 8*tg + g: conflict-free.
//   A_KC : A is (M,K) row-major (contraction contiguous). Else A is (K,M) rm.
//   B_NC : B is (K,N) row-major. Else B is (N,K) rm (contraction contiguous).
// M, Nn multiples of 128; K multiple of 16.
// ---------------------------------------------------------------------------
template <bool A_KC, bool B_NC>
__global__ void __launch_bounds__(256, 2)
tc_gemm(const float* __restrict__ A, const float* __restrict__ B,
        float* __restrict__ C, int M, int Nn, int K,
        int lda, int ldb, int ldc,
        long long sA, long long sB, long long sC)
{
    __shared__ uint32_t As[2][16][136];
    __shared__ uint32_t Bs[2][16][136];

    const int t    = threadIdx.x;
    const int lane = t & 31;
    const int wid  = t >> 5;
    const int wm   = wid >> 2;       // 0..1  -> 64-row slab
    const int wn   = wid & 3;        // 0..3  -> 32-col slab
    const int g    = lane >> 2;      // 0..7
    const int tg   = lane & 3;       // 0..3

    A += (long long)blockIdx.z * sA;
    B += (long long)blockIdx.z * sB;
    C += (long long)blockIdx.z * sC;

    const int m0 = blockIdx.y * 128;
    const int n0 = blockIdx.x * 128;

    // ---- global->smem staging indices (2 float4 per thread per operand) ----
    long long aoff0, aoff1, boff0, boff1, aStep, bStep;
    if (A_KC) {                       // A[m][k], k contiguous
        int m_ = t >> 2, k4 = (t & 3) * 4;
        aoff0 = (long long)(m0 + m_) * lda + k4;
        aoff1 = (long long)(m0 + m_ + 64) * lda + k4;
        aStep = 16;
    } else {                          // A[k][m], m contiguous
        int kr = t >> 5, m4 = (t & 31) * 4;
        aoff0 = (long long)kr * lda + m0 + m4;
        aoff1 = (long long)(kr + 8) * lda + m0 + m4;
        aStep = 16LL * lda;
    }
    if (B_NC) {                       // B[k][n], n contiguous
        int kr = t >> 5, n4 = (t & 31) * 4;
        boff0 = (long long)kr * ldb + n0 + n4;
        boff1 = (long long)(kr + 8) * ldb + n0 + n4;
        bStep = 16LL * ldb;
    } else {                          // B[n][k], k contiguous
        int n_ = t >> 2, k4 = (t & 3) * 4;
        boff0 = (long long)(n0 + n_) * ldb + k4;
        boff1 = (long long)(n0 + n_ + 64) * ldb + k4;
        bStep = 16;
    }

    auto storeA = [&](int buf, float4 v0, float4 v1) {
        if constexpr (A_KC) {
            int m_ = t >> 2, k4 = (t & 3) * 4;
            As[buf][k4 + 0][m_] = f2tf32(v0.x);
            As[buf][k4 + 1][m_] = f2tf32(v0.y);
            As[buf][k4 + 2][m_] = f2tf32(v0.z);
            As[buf][k4 + 3][m_] = f2tf32(v0.w);
            As[buf][k4 + 0][m_ + 64] = f2tf32(v1.x);
            As[buf][k4 + 1][m_ + 64] = f2tf32(v1.y);
            As[buf][k4 + 2][m_ + 64] = f2tf32(v1.z);
            As[buf][k4 + 3][m_ + 64] = f2tf32(v1.w);
        } else {
            int kr = t >> 5, m4 = (t & 31) * 4;
            uint4 u0 = make_uint4(f2tf32(v0.x), f2tf32(v0.y), f2tf32(v0.z), f2tf32(v0.w));
            uint4 u1 = make_uint4(f2tf32(v1.x), f2tf32(v1.y), f2tf32(v1.z), f2tf32(v1.w));
            *(uint4*)&As[buf][kr][m4]     = u0;
            *(uint4*)&As[buf][kr + 8][m4] = u1;
        }
    };
    auto storeB = [&](int buf, float4 v0, float4 v1) {
        if constexpr (B_NC) {
            int kr = t >> 5, n4 = (t & 31) * 4;
            uint4 u0 = make_uint4(f2tf32(v0.x), f2tf32(v0.y), f2tf32(v0.z), f2tf32(v0.w));
            uint4 u1 = make_uint4(f2tf32(v1.x), f2tf32(v1.y), f2tf32(v1.z), f2tf32(v1.w));
            *(uint4*)&Bs[buf][kr][n4]     = u0;
            *(uint4*)&Bs[buf][kr + 8][n4] = u1;
        } else {
            int n_ = t >> 2, k4 = (t & 3) * 4;
            Bs[buf][k4 + 0][n_] = f2tf32(v0.x);
            Bs[buf][k4 + 1][n_] = f2tf32(v0.y);
            Bs[buf][k4 + 2][n_] = f2tf32(v0.z);
            Bs[buf][k4 + 3][n_] = f2tf32(v0.w);
            Bs[buf][k4 + 0][n_ + 64] = f2tf32(v1.x);
            Bs[buf][k4 + 1][n_ + 64] = f2tf32(v1.y);
            Bs[buf][k4 + 2][n_ + 64] = f2tf32(v1.z);
            Bs[buf][k4 + 3][n_ + 64] = f2tf32(v1.w);
        }
    };

    // ---- prologue: stage 0 ----
    {
        float4 a0 = *(const float4*)(A + aoff0);
        float4 a1 = *(const float4*)(A + aoff1);
        float4 b0 = *(const float4*)(B + boff0);
        float4 b1 = *(const float4*)(B + boff1);
        storeA(0, a0, a1);
        storeB(0, b0, b1);
    }
    __syncthreads();

    float acc[4][4][4];
#pragma unroll
    for (int mi = 0; mi < 4; mi++)
#pragma unroll
        for (int ni = 0; ni < 4; ni++)
#pragma unroll
            for (int r = 0; r < 4; r++) acc[mi][ni][r] = 0.0f;

    const int nT = K >> 4;
    int buf = 0;

    for (int kt = 0; kt < nT; kt++) {
        const bool nxt = (kt + 1 < nT);
        float4 na0, na1, nb0, nb1;
        if (nxt) {
            aoff0 += aStep; aoff1 += aStep;
            boff0 += bStep; boff1 += bStep;
            na0 = *(const float4*)(A + aoff0);
            na1 = *(const float4*)(A + aoff1);
            nb0 = *(const float4*)(B + boff0);
            nb1 = *(const float4*)(B + boff1);
        }

#pragma unroll
        for (int kk = 0; kk < 16; kk += 8) {
            uint32_t afr[4][4], bfr[4][2];
#pragma unroll
            for (int mi = 0; mi < 4; mi++) {
                int mc = wm * 64 + mi * 16 + g;
                afr[mi][0] = As[buf][kk + tg][mc];
                afr[mi][1] = As[buf][kk + tg][mc + 8];
                afr[mi][2] = As[buf][kk + tg + 4][mc];
                afr[mi][3] = As[buf][kk + tg + 4][mc + 8];
            }
#pragma unroll
            for (int ni = 0; ni < 4; ni++) {
                int nc = wn * 32 + ni * 8 + g;
                bfr[ni][0] = Bs[buf][kk + tg][nc];
                bfr[ni][1] = Bs[buf][kk + tg + 4][nc];
            }
#pragma unroll
            for (int mi = 0; mi < 4; mi++)
#pragma unroll
                for (int ni = 0; ni < 4; ni++)
                    mma8(acc[mi][ni], afr[mi], bfr[ni]);
        }

        if (nxt) {
            storeA(buf ^ 1, na0, na1);
            storeB(buf ^ 1, nb0, nb1);
            __syncthreads();
            buf ^= 1;
        }
    }

    // ---- epilogue ----
#pragma unroll
    for (int mi = 0; mi < 4; mi++) {
#pragma unroll
        for (int ni = 0; ni < 4; ni++) {
            int row = m0 + wm * 64 + mi * 16 + g;
            int col = n0 + wn * 32 + ni * 8 + 2 * tg;
            float2 lo = make_float2(acc[mi][ni][0], acc[mi][ni][1]);
            float2 hi = make_float2(acc[mi][ni][2], acc[mi][ni][3]);
            *(float2*)&C[(long long)row * ldc + col]       = lo;
            *(float2*)&C[(long long)(row + 8) * ldc + col] = hi;
        }
    }
}

// ---------------------------------------------------------------------------
// Scalar fp32 SGEMM (R6 version, reverted from FFMA2): used for the
// projection and mask GEMMs to keep input/output quantization out of the
// error budget. 128x128 tile, BK=8, 8x8 frags, double-buffered.
// ---------------------------------------------------------------------------
template <bool A_KC, bool B_NC>
__global__ void __launch_bounds__(256)
sgemm128(const float* __restrict__ A, const float* __restrict__ B,
         float* __restrict__ C, int M, int Nn, int K,
         int lda, int ldb, int ldc,
         long long sA, long long sB, long long sC)
{
    __shared__ float As[2][8][132];
    __shared__ float Bs[2][8][132];

    const int t  = threadIdx.x;
    const int tx = t & 15;
    const int ty = t >> 4;

    A += (long long)blockIdx.z * sA;
    B += (long long)blockIdx.z * sB;
    C += (long long)blockIdx.z * sC;

    const int m0 = blockIdx.y * 128;
    const int n0 = blockIdx.x * 128;

    int a_m, a_k, b_n, b_k;
    if (A_KC) { a_m = t >> 1;  a_k = (t & 1) * 4; }
    else      { a_k = t >> 5;  a_m = (t & 31) * 4; }
    if (B_NC) { b_k = t >> 5;  b_n = (t & 31) * 4; }
    else      { b_n = t >> 1;  b_k = (t & 1) * 4; }

    const float* Ag;
    if (A_KC) Ag = A + (long long)(m0 + a_m) * lda + a_k;
    else      Ag = A + (long long)a_k * lda + m0 + a_m;
    const float* Bg;
    if (B_NC) Bg = B + (long long)b_k * ldb + n0 + b_n;
    else      Bg = B + (long long)(n0 + b_n) * ldb + b_k;

    const long long aStep = A_KC ? 8LL : 8LL * lda;
    const long long bStep = B_NC ? 8LL * ldb : 8LL;

    float4 ra = *(const float4*)Ag;
    float4 rb = *(const float4*)Bg;
    if (A_KC) {
        As[0][a_k + 0][a_m] = ra.x; As[0][a_k + 1][a_m] = ra.y;
        As[0][a_k + 2][a_m] = ra.z; As[0][a_k + 3][a_m] = ra.w;
    } else {
        *(float4*)&As[0][a_k][a_m] = ra;
    }
    if (B_NC) {
        *(float4*)&Bs[0][b_k][b_n] = rb;
    } else {
        Bs[0][b_k + 0][b_n] = rb.x; Bs[0][b_k + 1][b_n] = rb.y;
        Bs[0][b_k + 2][b_n] = rb.z; Bs[0][b_k + 3][b_n] = rb.w;
    }
    __syncthreads();

    float acc[8][8];
#pragma unroll
    for (int i = 0; i < 8; i++)
#pragma unroll
        for (int j = 0; j < 8; j++) acc[i][j] = 0.0f;

    const int nT = K >> 3;
    int buf = 0;

    for (int kt = 0; kt < nT; kt++) {
        float4 na, nb;
        const bool has_next = (kt + 1 < nT);
        if (has_next) {
            Ag += aStep; Bg += bStep;
            na = *(const float4*)Ag;
            nb = *(const float4*)Bg;
        }
#pragma unroll
        for (int k = 0; k < 8; k++) {
            float af[8], bf[8];
            *(float4*)&af[0] = *(const float4*)&As[buf][k][ty * 8];
            *(float4*)&af[4] = *(const float4*)&As[buf][k][ty * 8 + 4];
            *(float4*)&bf[0] = *(const float4*)&Bs[buf][k][tx * 8];
            *(float4*)&bf[4] = *(const float4*)&Bs[buf][k][tx * 8 + 4];
#pragma unroll
            for (int i = 0; i < 8; i++)
#pragma unroll
                for (int j = 0; j < 8; j++)
                    acc[i][j] = fmaf(af[i], bf[j], acc[i][j]);
        }
        if (has_next) {
            const int nbuf = buf ^ 1;
            if (A_KC) {
                As[nbuf][a_k + 0][a_m] = na.x; As[nbuf][a_k + 1][a_m] = na.y;
                As[nbuf][a_k + 2][a_m] = na.z; As[nbuf][a_k + 3][a_m] = na.w;
            } else {
                *(float4*)&As[nbuf][a_k][a_m] = na;
            }
            if (B_NC) {
                *(float4*)&Bs[nbuf][b_k][b_n] = nb;
            } else {
                Bs[nbuf][b_k + 0][b_n] = nb.x; Bs[nbuf][b_k + 1][b_n] = nb.y;
                Bs[nbuf][b_k + 2][b_n] = nb.z; Bs[nbuf][b_k + 3][b_n] = nb.w;
            }
            __syncthreads();
            buf = nbuf;
        }
    }

#pragma unroll
    for (int i = 0; i < 8; i++) {
        long long row = (long long)(m0 + ty * 8 + i) * ldc + n0 + tx * 8;
        float4 c0 = make_float4(acc[i][0], acc[i][1], acc[i][2], acc[i][3]);
        float4 c1 = make_float4(acc[i][4], acc[i][5], acc[i][6], acc[i][7]);
        *(float4*)&C[row]     = c0;
        *(float4*)&C[row + 4] = c1;
    }
}

// ---------------------------------------------------------------------------
// Softmax over rows of 4096 (HBM-bound at 78.9% already — unchanged).
// Polynomial exp instead of MUFU.EX2 (EX2 rt=8/SMSP on sm_103a).
// ---------------------------------------------------------------------------
__device__ __forceinline__ float fast_exp(float x) {
    float t = x * 1.4426950408889634f;
    t = fmaxf(t, -126.0f);
    float fi = floorf(t);
    float fr = (t - fi) * 0.6931471805599453f;
    float p = 1.0f / 720.0f;
    p = fmaf(p, fr, 1.0f / 120.0f);
    p = fmaf(p, fr, 1.0f / 24.0f);
    p = fmaf(p, fr, 1.0f / 6.0f);
    p = fmaf(p, fr, 0.5f);
    p = fmaf(p, fr, 1.0f);
    p = fmaf(p, fr, 1.0f);
    int n = (int)fi;
    return p * __int_as_float((n + 127) << 23);
}

__global__ void __launch_bounds__(256) softmax_kernel(float* __restrict__ f) {
    float* p = f + (long long)blockIdx.x * NN_;
    const int t = threadIdx.x;
    float v[16];
    float mx = -3.4e38f;
#pragma unroll
    for (int i = 0; i < 16; i++) {
        v[i] = p[i * 256 + t];
        mx = fmaxf(mx, v[i]);
    }
#pragma unroll
    for (int o = 16; o > 0; o >>= 1)
        mx = fmaxf(mx, __shfl_xor_sync(0xffffffffu, mx, o));
    __shared__ float sred[8];
    if ((t & 31) == 0) sred[t >> 5] = mx;
    __syncthreads();
#pragma unroll
    for (int i = 0; i < 8; i++) mx = fmaxf(mx, sred[i]);
    __syncthreads();

    float s = 0.0f;
#pragma unroll
    for (int i = 0; i < 16; i++) { v[i] = fast_exp(v[i] - mx); s += v[i]; }
#pragma unroll
    for (int o = 16; o > 0; o >>= 1)
        s += __shfl_xor_sync(0xffffffffu, s, o);
    if ((t & 31) == 0) sred[t >> 5] = s;
    __syncthreads();
    s = 0.0f;
#pragma unroll
    for (int i = 0; i < 8; i++) s += sred[i];

    const float inv = 1.0f / s;
#pragma unroll
    for (int i = 0; i < 16; i++) p[i * 256 + t] = v[i] * inv;
}

// ---------------------------------------------------------------------------
// kernel_launch: graph-capturable (kernel launches only; no sync, no alloc)
// ---------------------------------------------------------------------------
extern "C" void kernel_launch(void* const* d_in, const int* in_sizes, int n_in,
                              void* d_out, int out_size) {
    (void)in_sizes; (void)n_in; (void)out_size;
    const float* x       = (const float*)d_in[0];
    const float* w_phi   = (const float*)d_in[1];
    const float* w_theta = (const float*)d_in[2];
    const float* w_g     = (const float*)d_in[3];
    const float* w_mask  = (const float*)d_in[4];
    float* out = (float*)d_out;

    float *wcat, *ptg, *f, *y;
    cudaGetSymbolAddress((void**)&wcat, g_w);
    cudaGetSymbolAddress((void**)&ptg,  g_ptg);
    cudaGetSymbolAddress((void**)&f,    g_f);
    cudaGetSymbolAddress((void**)&y,    g_y);

    // 1) concat projection weights -> one fused projection GEMM
    concat_w_kernel<<<512, 256>>>(w_phi, w_theta, w_g);

    // 2) [phi;theta;g] = Wcat(768x512) @ x[b](512x4096)  (fp32 scalar)
    sgemm128<true, true><<<dim3(32, 6, NB), 256>>>(
        wcat, x, ptg, 768, NN_, NC,
        NC, NN_, NN_, 0LL, (long long)NC * NN_, 768LL * NN_);

    // 3) f[n,m] = sum_c theta[c,n] * phi[c,m]   (TF32 tensor cores)
    tc_gemm<false, true><<<dim3(32, 32, NB), 256>>>(
        ptg + NCI * NN_, ptg, f, NN_, NN_, NCI,
        NN_, NN_, NN_, 768LL * NN_, 768LL * NN_, (long long)NN_ * NN_);

    // 4) softmax over last axis, in place
    softmax_kernel<<<NB * NN_, 256>>>(f);

    // 5) y[c,n] = sum_m g[c,m] * a[n,m]   (TF32 tensor cores)
    tc_gemm<true, false><<<dim3(32, 2, NB), 256>>>(
        ptg + 2 * NCI * NN_, f, y, NCI, NN_, NN_,
        NN_, NN_, NN_, 768LL * NN_, (long long)NN_ * NN_, (long long)NCI * NN_);

    // 6) out[o,n] = sum_c w_mask[o,c] * y[c,n]  (fp32 scalar)
    sgemm128<true, true><<<dim3(32, 4, NB), 256>>>(
        w_mask, y, out, NC, NN_, NCI,
        NCI, NN_, NN_, 0LL, (long long)NCI * NN_, (long long)NC * NN_);
}

// round 13
// speedup vs baseline: 3.6941x; 1.2421x over previous
#include <cuda_runtime.h>
#include <cuda_bf16.h>
#include <cstdint>

// Problem constants: B=4, C=512, H=W=64 -> N=4096, CI=256
#define NB   4
#define NC   512
#define NN_  4096
#define NCI  256
typedef __nv_bfloat16 bf16;

// ---------------------------------------------------------------------------
// Scratch (device globals: allocation inside kernel_launch is forbidden)
// ---------------------------------------------------------------------------
__device__ float g_w  [3 * NCI * NC];              // concat [w_phi; w_theta; w_g]  (768 x 512)
__device__ float g_ptg[NB * 3 * NCI * NN_];        // per batch: rows 0-255 phi, 256-511 theta, 512-767 g
__device__ float g_f  [(long long)NB * NN_ * NN_]; // attention scores / probs (268 MB)
__device__ float g_y  [NB * NCI * NN_];            // y = a @ g^T  (b, ci, N)

// ---------------------------------------------------------------------------
// Weight concat: one GEMM for all three projections
// ---------------------------------------------------------------------------
__global__ void concat_w_kernel(const float* __restrict__ a,
                                const float* __restrict__ b,
                                const float* __restrict__ c) {
    int i = blockIdx.x * 256 + threadIdx.x;
    g_w[i]           = a[i];
    g_w[i + 131072]  = b[i];
    g_w[i + 262144]  = c[i];
}

// ---------------------------------------------------------------------------
// MMA helpers (legacy mma.sync path — tcgen05 is not reachable: the harness
// builds PTX at .target sm_103 without the 'a' suffix, R12 finding)
// ---------------------------------------------------------------------------
__device__ __forceinline__ uint32_t f2tf32(float f) {
    uint32_t r;
    asm("cvt.rna.tf32.f32 %0, %1;" : "=r"(r) : "f"(f));
    return r;
}
__device__ __forceinline__ void mma8(float* d, const uint32_t* a, const uint32_t* b) {
    asm volatile(
        "mma.sync.aligned.m16n8k8.row.col.f32.tf32.tf32.f32 "
        "{%0,%1,%2,%3}, {%4,%5,%6,%7}, {%8,%9}, {%0,%1,%2,%3};"
        : "+f"(d[0]), "+f"(d[1]), "+f"(d[2]), "+f"(d[3])
        : "r"(a[0]), "r"(a[1]), "r"(a[2]), "r"(a[3]), "r"(b[0]), "r"(b[1]));
}
__device__ __forceinline__ void mma16bf(float* d, const uint32_t* a, const uint32_t* b) {
    asm volatile(
        "mma.sync.aligned.m16n8k16.row.col.f32.bf16.bf16.f32 "
        "{%0,%1,%2,%3}, {%4,%5,%6,%7}, {%8,%9}, {%0,%1,%2,%3};"
        : "+f"(d[0]), "+f"(d[1]), "+f"(d[2]), "+f"(d[3])
        : "r"(a[0]), "r"(a[1]), "r"(a[2]), "r"(a[3]), "r"(b[0]), "r"(b[1]));
}
// pack fp32 pair -> bf16x2 words (hi and lo residual), even elem in low half
__device__ __forceinline__ void pack_hl(float x, float y, uint32_t& ph, uint32_t& pl) {
    bf16 hx = __float2bfloat16(x), hy = __float2bfloat16(y);
    bf16 lx = __float2bfloat16(x - __bfloat162float(hx));
    bf16 ly = __float2bfloat16(y - __bfloat162float(hy));
    __nv_bfloat162 h2 = __halves2bfloat162(hx, hy);
    __nv_bfloat162 l2 = __halves2bfloat162(lx, ly);
    ph = *(uint32_t*)&h2;
    pl = *(uint32_t*)&l2;
}

// ---------------------------------------------------------------------------
// TF32 tensor-core GEMM (R9, unchanged — proven at 153 TF/s).
// Block tile 128x128, BK=16, 8 warps (2m x 4n), warp tile 64x32 via m16n8k8.
//   A_KC : A is (M,K) row-major. Else A is (K,M) rm.
//   B_NC : B is (K,N) row-major. Else B is (N,K) rm.
// ---------------------------------------------------------------------------
template <bool A_KC, bool B_NC>
__global__ void __launch_bounds__(256, 2)
tc_gemm(const float* __restrict__ A, const float* __restrict__ B,
        float* __restrict__ C, int M, int Nn, int K,
        int lda, int ldb, int ldc,
        long long sA, long long sB, long long sC)
{
    __shared__ uint32_t As[2][16][136];
    __shared__ uint32_t Bs[2][16][136];

    const int t    = threadIdx.x;
    const int lane = t & 31;
    const int wid  = t >> 5;
    const int wm   = wid >> 2;
    const int wn   = wid & 3;
    const int g    = lane >> 2;
    const int tg   = lane & 3;

    A += (long long)blockIdx.z * sA;
    B += (long long)blockIdx.z * sB;
    C += (long long)blockIdx.z * sC;

    const int m0 = blockIdx.y * 128;
    const int n0 = blockIdx.x * 128;

    long long aoff0, aoff1, boff0, boff1, aStep, bStep;
    if (A_KC) {
        int m_ = t >> 2, k4 = (t & 3) * 4;
        aoff0 = (long long)(m0 + m_) * lda + k4;
        aoff1 = (long long)(m0 + m_ + 64) * lda + k4;
        aStep = 16;
    } else {
        int kr = t >> 5, m4 = (t & 31) * 4;
        aoff0 = (long long)kr * lda + m0 + m4;
        aoff1 = (long long)(kr + 8) * lda + m0 + m4;
        aStep = 16LL * lda;
    }
    if (B_NC) {
        int kr = t >> 5, n4 = (t & 31) * 4;
        boff0 = (long long)kr * ldb + n0 + n4;
        boff1 = (long long)(kr + 8) * ldb + n0 + n4;
        bStep = 16LL * ldb;
    } else {
        int n_ = t >> 2, k4 = (t & 3) * 4;
        boff0 = (long long)(n0 + n_) * ldb + k4;
        boff1 = (long long)(n0 + n_ + 64) * ldb + k4;
        bStep = 16;
    }

    auto storeA = [&](int buf, float4 v0, float4 v1) {
        if constexpr (A_KC) {
            int m_ = t >> 2, k4 = (t & 3) * 4;
            As[buf][k4 + 0][m_] = f2tf32(v0.x);
            As[buf][k4 + 1][m_] = f2tf32(v0.y);
            As[buf][k4 + 2][m_] = f2tf32(v0.z);
            As[buf][k4 + 3][m_] = f2tf32(v0.w);
            As[buf][k4 + 0][m_ + 64] = f2tf32(v1.x);
            As[buf][k4 + 1][m_ + 64] = f2tf32(v1.y);
            As[buf][k4 + 2][m_ + 64] = f2tf32(v1.z);
            As[buf][k4 + 3][m_ + 64] = f2tf32(v1.w);
        } else {
            int kr = t >> 5, m4 = (t & 31) * 4;
            uint4 u0 = make_uint4(f2tf32(v0.x), f2tf32(v0.y), f2tf32(v0.z), f2tf32(v0.w));
            uint4 u1 = make_uint4(f2tf32(v1.x), f2tf32(v1.y), f2tf32(v1.z), f2tf32(v1.w));
            *(uint4*)&As[buf][kr][m4]     = u0;
            *(uint4*)&As[buf][kr + 8][m4] = u1;
        }
    };
    auto storeB = [&](int buf, float4 v0, float4 v1) {
        if constexpr (B_NC) {
            int kr = t >> 5, n4 = (t & 31) * 4;
            uint4 u0 = make_uint4(f2tf32(v0.x), f2tf32(v0.y), f2tf32(v0.z), f2tf32(v0.w));
            uint4 u1 = make_uint4(f2tf32(v1.x), f2tf32(v1.y), f2tf32(v1.z), f2tf32(v1.w));
            *(uint4*)&Bs[buf][kr][n4]     = u0;
            *(uint4*)&Bs[buf][kr + 8][n4] = u1;
        } else {
            int n_ = t >> 2, k4 = (t & 3) * 4;
            Bs[buf][k4 + 0][n_] = f2tf32(v0.x);
            Bs[buf][k4 + 1][n_] = f2tf32(v0.y);
            Bs[buf][k4 + 2][n_] = f2tf32(v0.z);
            Bs[buf][k4 + 3][n_] = f2tf32(v0.w);
            Bs[buf][k4 + 0][n_ + 64] = f2tf32(v1.x);
            Bs[buf][k4 + 1][n_ + 64] = f2tf32(v1.y);
            Bs[buf][k4 + 2][n_ + 64] = f2tf32(v1.z);
            Bs[buf][k4 + 3][n_ + 64] = f2tf32(v1.w);
        }
    };

    {
        float4 a0 = *(const float4*)(A + aoff0);
        float4 a1 = *(const float4*)(A + aoff1);
        float4 b0 = *(const float4*)(B + boff0);
        float4 b1 = *(const float4*)(B + boff1);
        storeA(0, a0, a1);
        storeB(0, b0, b1);
    }
    __syncthreads();

    float acc[4][4][4];
#pragma unroll
    for (int mi = 0; mi < 4; mi++)
#pragma unroll
        for (int ni = 0; ni < 4; ni++)
#pragma unroll
            for (int r = 0; r < 4; r++) acc[mi][ni][r] = 0.0f;

    const int nT = K >> 4;
    int buf = 0;

    for (int kt = 0; kt < nT; kt++) {
        const bool nxt = (kt + 1 < nT);
        float4 na0, na1, nb0, nb1;
        if (nxt) {
            aoff0 += aStep; aoff1 += aStep;
            boff0 += bStep; boff1 += bStep;
            na0 = *(const float4*)(A + aoff0);
            na1 = *(const float4*)(A + aoff1);
            nb0 = *(const float4*)(B + boff0);
            nb1 = *(const float4*)(B + boff1);
        }

#pragma unroll
        for (int kk = 0; kk < 16; kk += 8) {
            uint32_t afr[4][4], bfr[4][2];
#pragma unroll
            for (int mi = 0; mi < 4; mi++) {
                int mc = wm * 64 + mi * 16 + g;
                afr[mi][0] = As[buf][kk + tg][mc];
                afr[mi][1] = As[buf][kk + tg][mc + 8];
                afr[mi][2] = As[buf][kk + tg + 4][mc];
                afr[mi][3] = As[buf][kk + tg + 4][mc + 8];
            }
#pragma unroll
            for (int ni = 0; ni < 4; ni++) {
                int nc = wn * 32 + ni * 8 + g;
                bfr[ni][0] = Bs[buf][kk + tg][nc];
                bfr[ni][1] = Bs[buf][kk + tg + 4][nc];
            }
#pragma unroll
            for (int mi = 0; mi < 4; mi++)
#pragma unroll
                for (int ni = 0; ni < 4; ni++)
                    mma8(acc[mi][ni], afr[mi], bfr[ni]);
        }

        if (nxt) {
            storeA(buf ^ 1, na0, na1);
            storeB(buf ^ 1, nb0, nb1);
            __syncthreads();
            buf ^= 1;
        }
    }

#pragma unroll
    for (int mi = 0; mi < 4; mi++) {
#pragma unroll
        for (int ni = 0; ni < 4; ni++) {
            int row = m0 + wm * 64 + mi * 16 + g;
            int col = n0 + wn * 32 + ni * 8 + 2 * tg;
            float2 lo = make_float2(acc[mi][ni][0], acc[mi][ni][1]);
            float2 hi = make_float2(acc[mi][ni][2], acc[mi][ni][3]);
            *(float2*)&C[(long long)row * ldc + col]       = lo;
            *(float2*)&C[(long long)(row + 8) * ldc + col] = hi;
        }
    }
}

// ---------------------------------------------------------------------------
// BF16 3-term-split GEMM (replaces scalar sgemm128 for proj & mask):
// C = A@B with A = Ah+Al, B = Bh+Bl in bf16; acc += AhBh + AhBl + AlBh.
// Per-stage rel error ~1e-5 (vs 4.9e-4 tf32) at ~2x tf32 instruction rate.
// Layouts fixed: A (M,K) row-major, B (K,N) row-major. Tile 128x128, BK=16,
// mma.m16n8k16. SMEM words are packed bf16x2 along k (k-pair rows, 8 per
// tile), which makes fragment indexing identical to the tf32 kernel.
// ---------------------------------------------------------------------------
__global__ void __launch_bounds__(256, 2)
tc_gemm_bf3(const float* __restrict__ A, const float* __restrict__ B,
            float* __restrict__ C, int M, int Nn, int K,
            int lda, int ldb, int ldc,
            long long sA, long long sB, long long sC)
{
    __shared__ uint32_t Ash[2][8][136], Asl[2][8][136];
    __shared__ uint32_t Bsh[2][8][136], Bsl[2][8][136];

    const int t    = threadIdx.x;
    const int lane = t & 31;
    const int wid  = t >> 5;
    const int wm   = wid >> 2;
    const int wn   = wid & 3;
    const int g    = lane >> 2;
    const int tg   = lane & 3;

    A += (long long)blockIdx.z * sA;
    B += (long long)blockIdx.z * sB;
    C += (long long)blockIdx.z * sC;

    const int m0 = blockIdx.y * 128;
    const int n0 = blockIdx.x * 128;

    // A: thread (m_, k4): rows m_ and m_+64, 4 consecutive k
    const int a_m = t >> 2, a_k4 = (t & 3) * 4;
    // B: thread (kp, n4): rows 2kp and 2kp+1, 4 consecutive n
    const int b_kp = t >> 5, b_n4 = (t & 31) * 4;

    long long aoff0 = (long long)(m0 + a_m) * lda + a_k4;
    long long aoff1 = (long long)(m0 + a_m + 64) * lda + a_k4;
    long long boff0 = (long long)(2 * b_kp) * ldb + n0 + b_n4;
    long long boff1 = (long long)(2 * b_kp + 1) * ldb + n0 + b_n4;
    const long long aStep = 16, bStep = 16LL * ldb;

    auto stage = [&](int buf, float4 a0, float4 a1, float4 b0, float4 b1) {
        // A: pack along k (consecutive pair within this thread's float4)
        uint32_t h0, l0, h1, l1;
        int kp = a_k4 >> 1;
        pack_hl(a0.x, a0.y, h0, l0); pack_hl(a0.z, a0.w, h1, l1);
        Ash[buf][kp][a_m] = h0;     Asl[buf][kp][a_m] = l0;
        Ash[buf][kp + 1][a_m] = h1; Asl[buf][kp + 1][a_m] = l1;
        pack_hl(a1.x, a1.y, h0, l0); pack_hl(a1.z, a1.w, h1, l1);
        Ash[buf][kp][a_m + 64] = h0;     Asl[buf][kp][a_m + 64] = l0;
        Ash[buf][kp + 1][a_m + 64] = h1; Asl[buf][kp + 1][a_m + 64] = l1;
        // B: pack across the two k rows (even k in low half)
        const float* p0 = (const float*)&b0;
        const float* p1 = (const float*)&b1;
#pragma unroll
        for (int j = 0; j < 4; j++) {
            uint32_t ph, pl;
            pack_hl(p0[j], p1[j], ph, pl);
            Bsh[buf][b_kp][b_n4 + j] = ph;
            Bsl[buf][b_kp][b_n4 + j] = pl;
        }
    };

    {
        float4 a0 = *(const float4*)(A + aoff0);
        float4 a1 = *(const float4*)(A + aoff1);
        float4 b0 = *(const float4*)(B + boff0);
        float4 b1 = *(const float4*)(B + boff1);
        stage(0, a0, a1, b0, b1);
    }
    __syncthreads();

    float acc[4][4][4];
#pragma unroll
    for (int mi = 0; mi < 4; mi++)
#pragma unroll
        for (int ni = 0; ni < 4; ni++)
#pragma unroll
            for (int r = 0; r < 4; r++) acc[mi][ni][r] = 0.0f;

    const int nT = K >> 4;
    int buf = 0;

    for (int kt = 0; kt < nT; kt++) {
        const bool nxt = (kt + 1 < nT);
        float4 na0, na1, nb0, nb1;
        if (nxt) {
            aoff0 += aStep; aoff1 += aStep;
            boff0 += bStep; boff1 += bStep;
            na0 = *(const float4*)(A + aoff0);
            na1 = *(const float4*)(A + aoff1);
            nb0 = *(const float4*)(B + boff0);
            nb1 = *(const float4*)(B + boff1);
        }

        // one m16n8k16 covers the whole BK=16 tile
        uint32_t ah[4][4], al[4][4], bh[4][2], bl[4][2];
#pragma unroll
        for (int mi = 0; mi < 4; mi++) {
            int mc = wm * 64 + mi * 16 + g;
            ah[mi][0] = Ash[buf][tg][mc];     al[mi][0] = Asl[buf][tg][mc];
            ah[mi][1] = Ash[buf][tg][mc + 8]; al[mi][1] = Asl[buf][tg][mc + 8];
            ah[mi][2] = Ash[buf][tg + 4][mc]; al[mi][2] = Asl[buf][tg + 4][mc];
            ah[mi][3] = Ash[buf][tg + 4][mc + 8]; al[mi][3] = Asl[buf][tg + 4][mc + 8];
        }
#pragma unroll
        for (int ni = 0; ni < 4; ni++) {
            int nc = wn * 32 + ni * 8 + g;
            bh[ni][0] = Bsh[buf][tg][nc];     bl[ni][0] = Bsl[buf][tg][nc];
            bh[ni][1] = Bsh[buf][tg + 4][nc]; bl[ni][1] = Bsl[buf][tg + 4][nc];
        }
#pragma unroll
        for (int mi = 0; mi < 4; mi++)
#pragma unroll
            for (int ni = 0; ni < 4; ni++) {
                mma16bf(acc[mi][ni], ah[mi], bh[ni]);
                mma16bf(acc[mi][ni], ah[mi], bl[ni]);
                mma16bf(acc[mi][ni], al[mi], bh[ni]);
            }

        if (nxt) {
            stage(buf ^ 1, na0, na1, nb0, nb1);
            __syncthreads();
            buf ^= 1;
        }
    }

#pragma unroll
    for (int mi = 0; mi < 4; mi++) {
#pragma unroll
        for (int ni = 0; ni < 4; ni++) {
            int row = m0 + wm * 64 + mi * 16 + g;
            int col = n0 + wn * 32 + ni * 8 + 2 * tg;
            float2 lo = make_float2(acc[mi][ni][0], acc[mi][ni][1]);
            float2 hi = make_float2(acc[mi][ni][2], acc[mi][ni][3]);
            *(float2*)&C[(long long)row * ldc + col]       = lo;
            *(float2*)&C[(long long)(row + 8) * ldc + col] = hi;
        }
    }
}

// ---------------------------------------------------------------------------
// Softmax over rows of 4096 (HBM-bound at ~79% — unchanged).
// ---------------------------------------------------------------------------
__device__ __forceinline__ float fast_exp(float x) {
    float t = x * 1.4426950408889634f;
    t = fmaxf(t, -126.0f);
    float fi = floorf(t);
    float fr = (t - fi) * 0.6931471805599453f;
    float p = 1.0f / 720.0f;
    p = fmaf(p, fr, 1.0f / 120.0f);
    p = fmaf(p, fr, 1.0f / 24.0f);
    p = fmaf(p, fr, 1.0f / 6.0f);
    p = fmaf(p, fr, 0.5f);
    p = fmaf(p, fr, 1.0f);
    p = fmaf(p, fr, 1.0f);
    return p * __int_as_float(((int)fi + 127) << 23);
}

__global__ void __launch_bounds__(256) softmax_kernel(float* __restrict__ f) {
    float* p = f + (long long)blockIdx.x * NN_;
    const int t = threadIdx.x;
    float v[16];
    float mx = -3.4e38f;
#pragma unroll
    for (int i = 0; i < 16; i++) {
        v[i] = p[i * 256 + t];
        mx = fmaxf(mx, v[i]);
    }
#pragma unroll
    for (int o = 16; o > 0; o >>= 1)
        mx = fmaxf(mx, __shfl_xor_sync(0xffffffffu, mx, o));
    __shared__ float sred[8];
    if ((t & 31) == 0) sred[t >> 5] = mx;
    __syncthreads();
#pragma unroll
    for (int i = 0; i < 8; i++) mx = fmaxf(mx, sred[i]);
    __syncthreads();

    float s = 0.0f;
#pragma unroll
    for (int i = 0; i < 16; i++) { v[i] = fast_exp(v[i] - mx); s += v[i]; }
#pragma unroll
    for (int o = 16; o > 0; o >>= 1)
        s += __shfl_xor_sync(0xffffffffu, s, o);
    if ((t & 31) == 0) sred[t >> 5] = s;
    __syncthreads();
    s = 0.0f;
#pragma unroll
    for (int i = 0; i < 8; i++) s += sred[i];

    const float inv = 1.0f / s;
#pragma unroll
    for (int i = 0; i < 16; i++) p[i * 256 + t] = v[i] * inv;
}

// ---------------------------------------------------------------------------
// kernel_launch: graph-capturable (kernel launches only; no sync, no alloc)
// ---------------------------------------------------------------------------
extern "C" void kernel_launch(void* const* d_in, const int* in_sizes, int n_in,
                              void* d_out, int out_size) {
    (void)in_sizes; (void)n_in; (void)out_size;
    const float* x       = (const float*)d_in[0];
    const float* w_phi   = (const float*)d_in[1];
    const float* w_theta = (const float*)d_in[2];
    const float* w_g     = (const float*)d_in[3];
    const float* w_mask  = (const float*)d_in[4];
    float* out = (float*)d_out;

    float *wcat, *ptg, *f, *y;
    cudaGetSymbolAddress((void**)&wcat, g_w);
    cudaGetSymbolAddress((void**)&ptg,  g_ptg);
    cudaGetSymbolAddress((void**)&f,    g_f);
    cudaGetSymbolAddress((void**)&y,    g_y);

    // 1) concat projection weights -> one fused projection GEMM
    concat_w_kernel<<<512, 256>>>(w_phi, w_theta, w_g);

    // 2) [phi;theta;g] = Wcat(768x512) @ x[b](512x4096)  (bf16 3-term split)
    tc_gemm_bf3<<<dim3(32, 6, NB), 256>>>(
        wcat, x, ptg, 768, NN_, NC,
        NC, NN_, NN_, 0LL, (long long)NC * NN_, 768LL * NN_);

    // 3) f[n,m] = sum_c theta[c,n] * phi[c,m]   (tf32)
    tc_gemm<false, true><<<dim3(32, 32, NB), 256>>>(
        ptg + NCI * NN_, ptg, f, NN_, NN_, NCI,
        NN_, NN_, NN_, 768LL * NN_, 768LL * NN_, (long long)NN_ * NN_);

    // 4) softmax over last axis, in place
    softmax_kernel<<<NB * NN_, 256>>>(f);

    // 5) y[c,n] = sum_m g[c,m] * a[n,m]   (tf32)
    tc_gemm<true, false><<<dim3(32, 2, NB), 256>>>(
        ptg + 2 * NCI * NN_, f, y, NCI, NN_, NN_,
        NN_, NN_, NN_, 768LL * NN_, (long long)NN_ * NN_, (long long)NCI * NN_);

    // 6) out[o,n] = sum_c w_mask[o,c] * y[c,n]  (bf16 3-term split)
    tc_gemm_bf3<<<dim3(32, 4, NB), 256>>>(
        w_mask, y, out, NC, NN_, NCI,
        NCI, NN_, NN_, 0LL, (long long)NCI * NN_, (long long)NC * NN_);
}